// round 6
// baseline (speedup 1.0000x reference)
#include <cuda_runtime.h>
#include <cstdint>

#define Bsz 4
#define Cch 512
#define MID 64
#define HWc 16384
#define PROJ_M 640
#define NEGV (-1e30f)

// ---------------- scratch ----------------------------------------------------
__device__ __align__(16) float g_proj [(size_t)Bsz*PROJ_M*HWc];
__device__ __align__(16) float g_projT[(size_t)Bsz*PROJ_M*HWc];
__device__ __align__(16) float g_eH[(size_t)Bsz*128*HWc];
__device__ __align__(16) float g_eW[(size_t)Bsz*128*HWc];
__device__ __align__(16) float g_outHt[(size_t)Bsz*Cch*HWc];

// ---------------- helpers ------------------------------------------------------
__device__ __forceinline__ void mma_tf32(float* c, const uint32_t* a, uint32_t b0, uint32_t b1){
    asm volatile(
        "mma.sync.aligned.m16n8k8.row.col.f32.tf32.tf32.f32 "
        "{%0,%1,%2,%3}, {%4,%5,%6,%7}, {%8,%9}, {%0,%1,%2,%3};"
        : "+f"(c[0]),"+f"(c[1]),"+f"(c[2]),"+f"(c[3])
        : "r"(a[0]),"r"(a[1]),"r"(a[2]),"r"(a[3]),"r"(b0),"r"(b1));
}
__device__ __forceinline__ uint32_t sptr(const void* p){
    return (uint32_t)__cvta_generic_to_shared(p);
}
__device__ __forceinline__ void cpa16(uint32_t s, const void* g){
    asm volatile("cp.async.ca.shared.global [%0], [%1], 16;" :: "r"(s), "l"(g));
}
#define CP_COMMIT() asm volatile("cp.async.commit_group;")
#define CP_WAIT(n)  asm volatile("cp.async.wait_group %0;" :: "n"(n))

// ---------------- projection: proj[b] = Wall(640x512) @ x[b](512x16384) ------
// grid (m-blocks=5, n-blocks=128, B): adjacent blocks share the X n-chunk via L2.
// block 128x128, BK=16, 3-stage cp.async, one sync/iter; warps 2x4, tile 64x32.
__global__ void proj_tf32(const float* __restrict__ Wq, const float* __restrict__ Wk,
                          const float* __restrict__ Wv, const float* __restrict__ X,
                          float* __restrict__ Out){
    const int b = blockIdx.z;
    const int m0blk = blockIdx.x * 128;
    const float* Bg = X + (size_t)b*Cch*HWc + blockIdx.y*128;
    float* Cg = Out + ((size_t)b*PROJ_M + m0blk)*HWc + blockIdx.y*128;

    __shared__ float As[3][128*20];   // [m][k] stride 20
    __shared__ float Bs[3][16*136];   // [k][n] stride 136

    const int tid = threadIdx.x, lane = tid & 31, warp = tid >> 5;
    const int g = lane >> 2, t4 = lane & 3;
    const int wr = warp >> 2, wc = warp & 3;

    const float* arow[2]; uint32_t adst[3][2];
    const float* brow[2]; uint32_t bdst[3][2];
    #pragma unroll
    for (int i = 0; i < 2; i++){
        int e = tid + i*256;
        int r = e >> 2, c = e & 3;
        int grow = m0blk + r;
        arow[i] = (grow < 64  ? Wq + (size_t)grow*Cch
                 : grow < 128 ? Wk + (size_t)(grow-64)*Cch
                              : Wv + (size_t)(grow-128)*Cch) + c*4;
        int rb2 = e >> 5, cb = e & 31;
        brow[i] = Bg + (size_t)rb2*HWc + cb*4;
        #pragma unroll
        for (int s = 0; s < 3; s++){
            adst[s][i] = sptr(&As[s][r*20 + c*4]);
            bdst[s][i] = sptr(&Bs[s][rb2*136 + cb*4]);
        }
    }

    float acc[4][4][4] = {};
    const int NIT = Cch/16;

    // prologue: stages 0,1
    #pragma unroll
    for (int s = 0; s < 2; s++){
        const int k0 = s*16;
        #pragma unroll
        for (int i = 0; i < 2; i++){
            cpa16(adst[s][i], arow[i] + k0);
            cpa16(bdst[s][i], brow[i] + (size_t)k0*HWc);
        }
        CP_COMMIT();
    }

    for (int it = 0; it < NIT; it++){
        // tail drain: on the final iteration only one group is pending, so
        // wait_group(1) would NOT wait — must use wait_group(0) there.
        if (it == NIT-1) { CP_WAIT(0); } else { CP_WAIT(1); }
        __syncthreads();
        if (it + 2 < NIT){
            const int s = (it+2) % 3;
            const int k0 = (it+2)*16;
            #pragma unroll
            for (int i = 0; i < 2; i++){
                cpa16(adst[s][i], arow[i] + k0);
                cpa16(bdst[s][i], brow[i] + (size_t)k0*HWc);
            }
            CP_COMMIT();
        }
        const float* Ac = As[it % 3];
        const float* Bc = Bs[it % 3];
        #pragma unroll
        for (int ks = 0; ks < 2; ks++){
            uint32_t a[4][4], bb[4][2];
            #pragma unroll
            for (int mt = 0; mt < 4; mt++){
                int rb = wr*64 + mt*16;
                a[mt][0] = __float_as_uint(Ac[(rb+g)*20   + ks*8 + t4]);
                a[mt][1] = __float_as_uint(Ac[(rb+g+8)*20 + ks*8 + t4]);
                a[mt][2] = __float_as_uint(Ac[(rb+g)*20   + ks*8 + t4 + 4]);
                a[mt][3] = __float_as_uint(Ac[(rb+g+8)*20 + ks*8 + t4 + 4]);
            }
            #pragma unroll
            for (int nt = 0; nt < 4; nt++){
                int nb = wc*32 + nt*8;
                bb[nt][0] = __float_as_uint(Bc[(ks*8+t4)*136   + nb + g]);
                bb[nt][1] = __float_as_uint(Bc[(ks*8+t4+4)*136 + nb + g]);
            }
            #pragma unroll
            for (int mt = 0; mt < 4; mt++)
                #pragma unroll
                for (int nt = 0; nt < 4; nt++)
                    mma_tf32(acc[mt][nt], a[mt], bb[nt][0], bb[nt][1]);
        }
    }
    __syncthreads();
    #pragma unroll
    for (int mt = 0; mt < 4; mt++)
        #pragma unroll
        for (int nt = 0; nt < 4; nt++){
            int row = wr*64 + mt*16 + g;
            int col = wc*32 + nt*8 + t4*2;
            float2 u0 = { acc[mt][nt][0], acc[mt][nt][1] };
            float2 u1 = { acc[mt][nt][2], acc[mt][nt][3] };
            *(float2*)(Cg + (size_t)row*HWc + col)     = u0;
            *(float2*)(Cg + (size_t)(row+8)*HWc + col) = u1;
        }
}

// ---------------- 128x128 per-plane fp32 transpose, 64x64 float4 tiles --------
__global__ void transpose128v(const float* __restrict__ in, float* __restrict__ out){
    __shared__ float t[64][65];
    const size_t p = blockIdx.z;
    const float* ip = in  + p*HWc;
    float*       op = out + p*HWc;
    const int x0 = blockIdx.x*64, y0 = blockIdx.y*64;
    const int tx = threadIdx.x & 15, ty = threadIdx.x >> 4;
    #pragma unroll
    for (int r = 0; r < 64; r += 16){
        float4 v = *(const float4*)(ip + (size_t)(y0+ty+r)*128 + x0 + tx*4);
        float* d = &t[ty+r][tx*4];
        d[0]=v.x; d[1]=v.y; d[2]=v.z; d[3]=v.w;
    }
    __syncthreads();
    #pragma unroll
    for (int r = 0; r < 64; r += 16){
        float4 o = { t[tx*4+0][ty+r], t[tx*4+1][ty+r],
                     t[tx*4+2][ty+r], t[tx*4+3][ty+r] };
        *(float4*)(op + (size_t)(x0+ty+r)*128 + y0 + tx*4) = o;
    }
}

// ---------------- gram: E[i,j] = sum_m Q[m,i]*K[m,j], 2-stage preissued -------
// blockIdx.y: 0 -> eH from projT, 1 -> eW from proj
__global__ void gram_tf32(const float* __restrict__ proj, const float* __restrict__ projT,
                          float* __restrict__ eH, float* __restrict__ eW){
    const float* P = blockIdx.y ? proj : projT;
    float* E = blockIdx.y ? eW : eH;
    const int bl = blockIdx.x, b = bl >> 7, line = bl & 127;
    const float* qb = P + (size_t)(b*PROJ_M)*HWc + line*128;
    const float* kb = qb + (size_t)MID*HWc;

    __shared__ float Qs[2][32*136];
    __shared__ float Ks[2][32*136];

    const int tid = threadIdx.x, lane = tid & 31, warp = tid >> 5;
    const int g = lane >> 2, t4 = lane & 3;
    const int wr = warp >> 2, wc = warp & 3;

    // prologue: both stages
    #pragma unroll
    for (int s = 0; s < 2; s++){
        #pragma unroll
        for (int i = 0; i < 4; i++){
            int e = tid + i*256, r = e >> 5, c = e & 31;
            cpa16(sptr(&Qs[s][r*136 + c*4]), qb + (size_t)(s*32+r)*HWc + c*4);
            cpa16(sptr(&Ks[s][r*136 + c*4]), kb + (size_t)(s*32+r)*HWc + c*4);
        }
        CP_COMMIT();
    }

    float acc[4][4][4] = {};

    #pragma unroll
    for (int st = 0; st < 2; st++){
        if (st == 0) { CP_WAIT(1); } else { CP_WAIT(0); }
        __syncthreads();
        const float* Qc = Qs[st];
        const float* Kc = Ks[st];
        #pragma unroll
        for (int ks = 0; ks < 4; ks++){
            uint32_t a[4][4], bb[4][2];
            #pragma unroll
            for (int mt = 0; mt < 4; mt++){
                int rb = wr*64 + mt*16;
                a[mt][0] = __float_as_uint(Qc[(ks*8+t4)*136   + rb + g]);
                a[mt][1] = __float_as_uint(Qc[(ks*8+t4)*136   + rb + g + 8]);
                a[mt][2] = __float_as_uint(Qc[(ks*8+t4+4)*136 + rb + g]);
                a[mt][3] = __float_as_uint(Qc[(ks*8+t4+4)*136 + rb + g + 8]);
            }
            #pragma unroll
            for (int nt = 0; nt < 4; nt++){
                int nb = wc*32 + nt*8;
                bb[nt][0] = __float_as_uint(Kc[(ks*8+t4)*136   + nb + g]);
                bb[nt][1] = __float_as_uint(Kc[(ks*8+t4+4)*136 + nb + g]);
            }
            #pragma unroll
            for (int mt = 0; mt < 4; mt++)
                #pragma unroll
                for (int nt = 0; nt < 4; nt++)
                    mma_tf32(acc[mt][nt], a[mt], bb[nt][0], bb[nt][1]);
        }
    }
    float* eb = E + (size_t)bl*HWc;
    #pragma unroll
    for (int mt = 0; mt < 4; mt++)
        #pragma unroll
        for (int nt = 0; nt < 4; nt++){
            int row = wr*64 + mt*16 + g;
            int col = wc*32 + nt*8 + t4*2;
            float2 u0 = { acc[mt][nt][0], acc[mt][nt][1] };
            float2 u1 = { acc[mt][nt][2], acc[mt][nt][3] };
            *(float2*)&eb[(size_t)row*128 + col]     = u0;
            *(float2*)&eb[(size_t)(row+8)*128 + col] = u1;
        }
}

// ---------------- joint softmax over 256 scores, in-place fp32 ----------------
__global__ void softmax_kernel(float* __restrict__ eH, float* __restrict__ eW) {
    const int pix  = blockIdx.x*8 + (threadIdx.x >> 5);
    const int lane = threadIdx.x & 31;
    const int w = pix & 127, h = (pix >> 7) & 127, b = pix >> 14;

    float* ph = eH + ((size_t)((b*128 + w)*128 + h))*128 + lane*4;
    float* pw = eW + ((size_t)((b*128 + h)*128 + w))*128 + lane*4;
    float4 vh = *(float4*)ph;
    float4 vw = *(float4*)pw;

    const int d = h - lane*4;
    if (d >= 0 && d < 4) ((float*)&vh)[d] = NEGV;

    float mx = fmaxf(fmaxf(fmaxf(vh.x, vh.y), fmaxf(vh.z, vh.w)),
                     fmaxf(fmaxf(vw.x, vw.y), fmaxf(vw.z, vw.w)));
    #pragma unroll
    for (int o = 16; o; o >>= 1) mx = fmaxf(mx, __shfl_xor_sync(0xffffffffu, mx, o));

    vh.x = __expf(vh.x - mx); vh.y = __expf(vh.y - mx);
    vh.z = __expf(vh.z - mx); vh.w = __expf(vh.w - mx);
    vw.x = __expf(vw.x - mx); vw.y = __expf(vw.y - mx);
    vw.z = __expf(vw.z - mx); vw.w = __expf(vw.w - mx);

    float s = vh.x + vh.y + vh.z + vh.w + vw.x + vw.y + vw.z + vw.w;
    #pragma unroll
    for (int o = 16; o; o >>= 1) s += __shfl_xor_sync(0xffffffffu, s, o);
    const float inv = 1.0f / s;

    vh.x *= inv; vh.y *= inv; vh.z *= inv; vh.w *= inv;
    vw.x *= inv; vw.y *= inv; vw.z *= inv; vw.w *= inv;
    *(float4*)ph = vh;
    *(float4*)pw = vw;
}

// ---------------- apply: Out[c,i] = sum_j V[c,j]*P[i,j], 3-stage async --------
// blockIdx.z: 0 -> (projT, eH) -> outHt ; 1 -> (proj, eW) -> outW(d_out)
__global__ void apply_tf32(const float* __restrict__ proj, const float* __restrict__ projT,
                           const float* __restrict__ eH, const float* __restrict__ eW,
                           float* __restrict__ outHt, float* __restrict__ outW){
    const float* Vfull = blockIdx.z ? proj : projT;
    const float* Pm    = blockIdx.z ? eW : eH;
    float* Outp        = blockIdx.z ? outW : outHt;

    const int bl = blockIdx.y, b = bl >> 7, line = bl & 127;
    const float* Vb = Vfull + ((size_t)(b*PROJ_M + 128 + blockIdx.x*128))*HWc + line*128;
    const float* Pb = Pm + (size_t)bl*HWc;
    float* Ob = Outp + ((size_t)(b*Cch + blockIdx.x*128))*HWc + line*128;

    __shared__ float Vs[3][128*20];
    __shared__ float Ps[3][128*20];

    const int tid = threadIdx.x, lane = tid & 31, warp = tid >> 5;
    const int g = lane >> 2, t4 = lane & 3;
    const int wr = warp >> 2, wc = warp & 3;

    const float* vrow[2]; const float* prow[2];
    uint32_t vdst[3][2], pdst[3][2];
    #pragma unroll
    for (int i = 0; i < 2; i++){
        int e = tid + i*256;
        int r = e >> 2, c = e & 3;
        vrow[i] = Vb + (size_t)r*HWc + c*4;
        prow[i] = Pb + (size_t)r*128 + c*4;
        #pragma unroll
        for (int s = 0; s < 3; s++){
            vdst[s][i] = sptr(&Vs[s][r*20 + c*4]);
            pdst[s][i] = sptr(&Ps[s][r*20 + c*4]);
        }
    }

    float acc[4][4][4] = {};
    const int NIT = 128/16;

    #pragma unroll
    for (int s = 0; s < 2; s++){
        #pragma unroll
        for (int i = 0; i < 2; i++){
            cpa16(vdst[s][i], vrow[i] + s*16);
            cpa16(pdst[s][i], prow[i] + s*16);
        }
        CP_COMMIT();
    }

    for (int it = 0; it < NIT; it++){
        // tail drain (see proj_tf32): final iteration must wait_group(0).
        if (it == NIT-1) { CP_WAIT(0); } else { CP_WAIT(1); }
        __syncthreads();
        if (it + 2 < NIT){
            const int s = (it+2) % 3;
            const int j0 = (it+2)*16;
            #pragma unroll
            for (int i = 0; i < 2; i++){
                cpa16(vdst[s][i], vrow[i] + j0);
                cpa16(pdst[s][i], prow[i] + j0);
            }
            CP_COMMIT();
        }
        const float* Vc = Vs[it % 3];
        const float* Pc = Ps[it % 3];
        #pragma unroll
        for (int ks = 0; ks < 2; ks++){
            uint32_t a[4][4], bb[4][2];
            #pragma unroll
            for (int mt = 0; mt < 4; mt++){
                int rb = wr*64 + mt*16;
                a[mt][0] = __float_as_uint(Vc[(rb+g)*20   + ks*8 + t4]);
                a[mt][1] = __float_as_uint(Vc[(rb+g+8)*20 + ks*8 + t4]);
                a[mt][2] = __float_as_uint(Vc[(rb+g)*20   + ks*8 + t4 + 4]);
                a[mt][3] = __float_as_uint(Vc[(rb+g+8)*20 + ks*8 + t4 + 4]);
            }
            #pragma unroll
            for (int nt = 0; nt < 4; nt++){
                int nb = wc*32 + nt*8;
                bb[nt][0] = __float_as_uint(Pc[(nb+g)*20 + ks*8 + t4]);
                bb[nt][1] = __float_as_uint(Pc[(nb+g)*20 + ks*8 + t4 + 4]);
            }
            #pragma unroll
            for (int mt = 0; mt < 4; mt++)
                #pragma unroll
                for (int nt = 0; nt < 4; nt++)
                    mma_tf32(acc[mt][nt], a[mt], bb[nt][0], bb[nt][1]);
        }
    }
    __syncthreads();
    #pragma unroll
    for (int mt = 0; mt < 4; mt++)
        #pragma unroll
        for (int nt = 0; nt < 4; nt++){
            int row = wr*64 + mt*16 + g;
            int col = wc*32 + nt*8 + t4*2;
            float2 u0 = { acc[mt][nt][0], acc[mt][nt][1] };
            float2 u1 = { acc[mt][nt][2], acc[mt][nt][3] };
            *(float2*)(Ob + (size_t)row*HWc + col)     = u0;
            *(float2*)(Ob + (size_t)(row+8)*HWc + col) = u1;
        }
}

// ---------------- combine: out = gamma*(outHt^T + outW) + x -------------------
__global__ void combine_kernel(const float* __restrict__ outHt, const float* __restrict__ outW,
                               const float* __restrict__ x, const float* __restrict__ gamma,
                               float* __restrict__ out) {
    __shared__ float t[64][65];
    const size_t p = blockIdx.z;
    const float* hp = outHt + p*HWc;
    const int w0 = blockIdx.x*64, h0 = blockIdx.y*64;
    const int tx = threadIdx.x & 15, ty = threadIdx.x >> 4;
    #pragma unroll
    for (int r = 0; r < 64; r += 16){
        float4 v = *(const float4*)(hp + (size_t)(w0+ty+r)*128 + h0 + tx*4);
        float* d = &t[ty+r][tx*4];
        d[0]=v.x; d[1]=v.y; d[2]=v.z; d[3]=v.w;
    }
    __syncthreads();
    const float g = gamma[0];
    #pragma unroll
    for (int r = 0; r < 64; r += 16){
        const int h = h0 + ty + r;
        const size_t base = p*HWc + (size_t)h*128 + w0 + tx*4;
        float4 xr = *(const float4*)(x + base);
        float4 ow = *(const float4*)(outW + base);
        float4 o;
        o.x = g*(t[tx*4+0][ty+r] + ow.x) + xr.x;
        o.y = g*(t[tx*4+1][ty+r] + ow.y) + xr.y;
        o.z = g*(t[tx*4+2][ty+r] + ow.z) + xr.z;
        o.w = g*(t[tx*4+3][ty+r] + ow.w) + xr.w;
        *(float4*)(out + base) = o;
    }
}

// ---------------------------------------------------------------------------
extern "C" void kernel_launch(void* const* d_in, const int* in_sizes, int n_in,
                              void* d_out, int out_size) {
    (void)in_sizes; (void)n_in; (void)out_size;
    const float* x     = (const float*)d_in[0];
    const float* Wq    = (const float*)d_in[1];
    const float* Wk    = (const float*)d_in[2];
    const float* Wv    = (const float*)d_in[3];
    const float* gamma = (const float*)d_in[4];
    float* out = (float*)d_out;

    float *proj, *projT, *eH, *eW, *outHt;
    cudaGetSymbolAddress((void**)&proj,  g_proj);
    cudaGetSymbolAddress((void**)&projT, g_projT);
    cudaGetSymbolAddress((void**)&eH,    g_eH);
    cudaGetSymbolAddress((void**)&eW,    g_eW);
    cudaGetSymbolAddress((void**)&outHt, g_outHt);

    // 1) fused projection; grid x=m-blocks so adjacent blocks share X via L2
    proj_tf32<<<dim3(PROJ_M/128, HWc/128, Bsz), 256>>>(Wq, Wk, Wv, x, proj);

    // 2) plane transposes (H<->W for all 640 planes per batch)
    transpose128v<<<dim3(2,2,Bsz*PROJ_M), 256>>>(proj, projT);

    // 3) attention scores (y=0: eH from projT, y=1: eW from proj)
    gram_tf32<<<dim3(Bsz*128, 2), 256>>>(proj, projT, eH, eW);

    // 4) joint softmax (in-place, diag of eH masked)
    softmax_kernel<<<(Bsz*HWc)/8, 256>>>(eH, eW);

    // 5) apply attention (z=0 -> outHt, z=1 -> d_out)
    apply_tf32<<<dim3(Cch/128, Bsz*128, 2), 256>>>(proj, projT, eH, eW, outHt, out);

    // 6) combine
    combine_kernel<<<dim3(2,2,Bsz*Cch), 256>>>(outHt, out, x, gamma, out);
}